// round 9
// baseline (speedup 1.0000x reference)
#include <cuda_runtime.h>
#include <cuda_bf16.h>

// Problem constants (fixed shapes from the reference):
//   x: (B=8, C=3, H=1024, W=1024) fp32, GRID 8x8 -> tile 128x128, no padding
//   NUM_BINS=256, CLIP_LIMIT=40 -> max_val = 40*16384//256 = 2560
//   pixels per tile = 16384, T = 8*3*8*8 = 1536 tiles

#define IMG    1048576            // 1024*1024
#define NTILES 1536               // 8*3*8*8
#define PIXELS 16384              // 128*128
#define MAXVAL 2560               // clip limit in counts

// Per-tile LUT, fp32 integer values 0..255. 1536*256*4 = 1.5 MB (static scratch).
__device__ float g_lut[NTILES * 256];

// ---------------------------------------------------------------------------
// Kernel 1: per-tile histogram -> clip -> redistribute -> cumsum -> LUT
// One CTA per tile. 256 threads, 8 per-warp sub-histograms in shared.
// ---------------------------------------------------------------------------
__global__ __launch_bounds__(256) void clahe_hist_lut(const float* __restrict__ x) {
    __shared__ unsigned int h[8][256];   // per-warp sub-histograms
    __shared__ int red[256];             // reduction scratch
    __shared__ int sc[256];              // scan scratch
    __shared__ int s_total;

    const int tid  = threadIdx.x;
    const int warp = tid >> 5;

    #pragma unroll
    for (int w = 0; w < 8; ++w) h[w][tid] = 0u;
    __syncthreads();

    const int t  = blockIdx.x;           // tile id: (bc, ty, tx)
    const int tx = t & 7;
    const int ty = (t >> 3) & 7;
    const int bc = t >> 6;

    const float* base = x + (size_t)bc * IMG + (size_t)(ty * 128) * 1024 + tx * 128;

    // 16384 pixels = 4096 float4; 256 threads x 16 iterations
    #pragma unroll 4
    for (int i = 0; i < 16; ++i) {
        const int lin = tid + i * 256;   // 0..4095
        const int row = lin >> 5;        // 32 float4 per 128-wide row
        const int c4  = lin & 31;
        const float4 v = *reinterpret_cast<const float4*>(base + row * 1024 + c4 * 4);
        int b0 = min(max(__float2int_rz(v.x * 256.0f), 0), 255);
        int b1 = min(max(__float2int_rz(v.y * 256.0f), 0), 255);
        int b2 = min(max(__float2int_rz(v.z * 256.0f), 0), 255);
        int b3 = min(max(__float2int_rz(v.w * 256.0f), 0), 255);
        atomicAdd(&h[warp][b0], 1u);
        atomicAdd(&h[warp][b1], 1u);
        atomicAdd(&h[warp][b2], 1u);
        atomicAdd(&h[warp][b3], 1u);
    }
    __syncthreads();

    // Reduce sub-histograms; each thread owns one bin (no bank conflicts)
    unsigned int cnt = 0;
    #pragma unroll
    for (int w = 0; w < 8; ++w) cnt += h[w][tid];

    // Clip
    const int hc = min((int)cnt, MAXVAL);

    // Block reduction: total clipped mass
    red[tid] = hc;
    __syncthreads();
    #pragma unroll
    for (int off = 128; off > 0; off >>= 1) {
        if (tid < off) red[tid] += red[tid + off];
        __syncthreads();
    }
    if (tid == 0) s_total = red[0];
    __syncthreads();

    // Redistribute excess (all integer-exact, matching the fp32-exact reference math)
    const int clipped  = PIXELS - s_total;
    const int residual = clipped & 255;          // mod 256 (clipped >= 0)
    const int add      = (clipped - residual) >> 8;
    const int hf       = hc + add + ((tid < residual) ? 1 : 0);

    // Inclusive Hillis-Steele scan over 256 bins
    sc[tid] = hf;
    __syncthreads();
    #pragma unroll
    for (int off = 1; off < 256; off <<= 1) {
        const int u = (tid >= off) ? sc[tid - off] : 0;
        __syncthreads();
        sc[tid] += u;
        __syncthreads();
    }

    // LUT: floor(clip(cumsum * 255/16384, 0, 255)); 255/16384 is exact in binary
    const float cum = (float)sc[tid];
    const float lv  = floorf(fminf(cum * (255.0f / 16384.0f), 255.0f));
    g_lut[t * 256 + tid] = lv;
}

// ---------------------------------------------------------------------------
// Kernel 2: apply with bilinear LUT blending.
// One CTA per 64x64 quadrant: within a quadrant the (r0,r1,c0,c1) LUT quad is
// constant -> pack the 4 LUTs' bytes into one shared u32[256] so each pixel
// does ONE shared lookup instead of 4 scattered loads.
// ---------------------------------------------------------------------------
__global__ __launch_bounds__(256) void clahe_apply(const float* __restrict__ x,
                                                   float* __restrict__ out) {
    __shared__ unsigned int packed[256];
    __shared__ float wys[64];
    __shared__ float wxs[64];

    const int tid = threadIdx.x;
    const int q   = blockIdx.x;          // (bc, qy, qx), qy/qx in [0,16)
    const int qx  = q & 15;
    const int qy  = (q >> 4) & 15;
    const int bc  = q >> 8;

    // Tile-pair indices for this quadrant (j == qy / qx in the reference)
    const int r0 = (qy == 0) ? 0 : min((qy - 1) >> 1, 7);
    const int r1 = min(r0 + 1, 7);
    const int c0 = (qx == 0) ? 0 : min((qx - 1) >> 1, 7);
    const int c1 = min(c0 + 1, 7);

    // Pack the 4 LUTs (values are exact integers 0..255) into bytes A,B,C,D
    {
        const int lb = bc * 64;
        const float A = g_lut[(lb + r0 * 8 + c0) * 256 + tid];
        const float B = g_lut[(lb + r0 * 8 + c1) * 256 + tid];
        const float C = g_lut[(lb + r1 * 8 + c0) * 256 + tid];
        const float D = g_lut[(lb + r1 * 8 + c1) * 256 + tid];
        packed[tid] = (unsigned)A | ((unsigned)B << 8) |
                      ((unsigned)C << 16) | ((unsigned)D << 24);
    }

    // Per-row / per-col blend weights (exact division by 127 like the reference)
    if (tid < 64) {
        const int p = tid;
        wys[p] = (qy == 0) ? 1.0f
               : ((qy & 1) ? (float)(127 - p) : (float)(63 - p)) / 127.0f;
    } else if (tid < 128) {
        const int p = tid - 64;
        wxs[p] = (qx == 0) ? 1.0f
               : ((qx & 1) ? (float)(127 - p) : (float)(63 - p)) / 127.0f;
    }
    __syncthreads();

    const size_t boff = (size_t)bc * IMG + (size_t)(qy * 64) * 1024 + qx * 64;
    const float* inb  = x   + boff;
    float*       outb = out + boff;

    // 64x64 quadrant = 1024 float4; 256 threads x 4 iterations
    #pragma unroll
    for (int i = 0; i < 4; ++i) {
        const int lin = tid + i * 256;
        const int row = lin >> 4;        // 16 float4 per 64-wide row
        const int c4  = lin & 15;
        const float4 v = *reinterpret_cast<const float4*>(inb + row * 1024 + c4 * 4);

        const float wy  = wys[row];
        const float omy = 1.0f - wy;
        const int pxb   = c4 * 4;

        float4 o;
        {
            const int idx = min(max(__float2int_rz(v.x * 255.0f), 0), 255);
            const unsigned u = packed[idx];
            const float A = (float)(u & 255u),       B = (float)((u >> 8) & 255u);
            const float C = (float)((u >> 16) & 255u), D = (float)(u >> 24);
            const float wx = wxs[pxb + 0], omx = 1.0f - wx;
            o.x = (wy * (wx * A + omx * B) + omy * (wx * C + omx * D)) * (1.0f / 255.0f);
        }
        {
            const int idx = min(max(__float2int_rz(v.y * 255.0f), 0), 255);
            const unsigned u = packed[idx];
            const float A = (float)(u & 255u),       B = (float)((u >> 8) & 255u);
            const float C = (float)((u >> 16) & 255u), D = (float)(u >> 24);
            const float wx = wxs[pxb + 1], omx = 1.0f - wx;
            o.y = (wy * (wx * A + omx * B) + omy * (wx * C + omx * D)) * (1.0f / 255.0f);
        }
        {
            const int idx = min(max(__float2int_rz(v.z * 255.0f), 0), 255);
            const unsigned u = packed[idx];
            const float A = (float)(u & 255u),       B = (float)((u >> 8) & 255u);
            const float C = (float)((u >> 16) & 255u), D = (float)(u >> 24);
            const float wx = wxs[pxb + 2], omx = 1.0f - wx;
            o.z = (wy * (wx * A + omx * B) + omy * (wx * C + omx * D)) * (1.0f / 255.0f);
        }
        {
            const int idx = min(max(__float2int_rz(v.w * 255.0f), 0), 255);
            const unsigned u = packed[idx];
            const float A = (float)(u & 255u),       B = (float)((u >> 8) & 255u);
            const float C = (float)((u >> 16) & 255u), D = (float)(u >> 24);
            const float wx = wxs[pxb + 3], omx = 1.0f - wx;
            o.w = (wy * (wx * A + omx * B) + omy * (wx * C + omx * D)) * (1.0f / 255.0f);
        }
        *reinterpret_cast<float4*>(outb + row * 1024 + c4 * 4) = o;
    }
}

extern "C" void kernel_launch(void* const* d_in, const int* in_sizes, int n_in,
                              void* d_out, int out_size) {
    const float* x   = (const float*)d_in[0];
    float*       out = (float*)d_out;
    (void)in_sizes; (void)n_in; (void)out_size;

    clahe_hist_lut<<<NTILES, 256>>>(x);            // 1536 CTAs: tile LUTs
    clahe_apply<<<NTILES * 4, 256>>>(x, out);      // 6144 CTAs: 64x64 quadrants
}